// round 13
// baseline (speedup 1.0000x reference)
#include <cuda_runtime.h>
#include <cuda_bf16.h>
#include <cstdint>
#include <math.h>

#define N_NODES 50000
#define N_EDGES 800000
#define F 64          // F_IN == F_HID
#define KTOT 192      // x | tx1 | y
#define NOUT 128      // z (64) | h (64)
#define SCAN_TILE 1024
#define MAX_BLOCKS ((N_NODES + SCAN_TILE - 1) / SCAN_TILE + 1)

// ---------------- device scratch (allocation-free) ----------------
// Self-clean invariant: scan_phase1 zeroes g_count, scan_phase3 zeroes g_deg,
// so every kernel_launch call leaves them zeroed for the next call.
__device__ float g_deg[N_NODES];
__device__ float g_dis[N_NODES];
__device__ int   g_count[N_NODES];
__device__ int   g_rowptr[N_NODES + 1];
__device__ int   g_cursor[N_NODES];
__device__ int   g_bsum[MAX_BLOCKS];
__device__ __align__(16) int2 g_edge[N_EDGES];      // (src, norm-bits), dense CSR
__device__ __align__(16) float g_tx1[N_NODES * F];
__device__ __align__(16) __nv_bfloat16 g_Ahi[N_NODES * KTOT];
__device__ __align__(16) __nv_bfloat16 g_Alo[N_NODES * KTOT];

// ---------------- PTX helpers ----------------
__device__ __forceinline__ uint32_t smem_u32(const void* p) {
    uint32_t a;
    asm("{ .reg .u64 t; cvta.to.shared.u64 t, %1; cvt.u32.u64 %0, t; }" : "=r"(a) : "l"(p));
    return a;
}
__device__ __forceinline__ void ldsm4(uint32_t (&d)[4], uint32_t addr) {
    asm volatile("ldmatrix.sync.aligned.m8n8.x4.shared.b16 {%0,%1,%2,%3}, [%4];\n"
                 : "=r"(d[0]), "=r"(d[1]), "=r"(d[2]), "=r"(d[3]) : "r"(addr));
}
__device__ __forceinline__ void mma_bf16(float (&c)[4], const uint32_t (&a)[4],
                                         uint32_t b0, uint32_t b1) {
    asm volatile(
        "mma.sync.aligned.m16n8k16.row.col.f32.bf16.bf16.f32 "
        "{%0,%1,%2,%3}, {%4,%5,%6,%7}, {%8,%9}, {%0,%1,%2,%3};\n"
        : "+f"(c[0]), "+f"(c[1]), "+f"(c[2]), "+f"(c[3])
        : "r"(a[0]), "r"(a[1]), "r"(a[2]), "r"(a[3]), "r"(b0), "r"(b1));
}

// ---------------- kernels ----------------

__global__ void edge_pass1_kernel(const int* __restrict__ ei,
                                  const float* __restrict__ ew, int E) {
    int e = blockIdx.x * blockDim.x + threadIdx.x;
    if (e >= E) return;
    atomicAdd(&g_deg[ei[e]], ew[e]);
    atomicAdd(&g_count[ei[E + e]], 1);
}

// Phase 1: per-1024-tile local exclusive scan; tile total -> g_bsum.
// Also zeroes g_count (self-clean for next replay).
__global__ void scan_phase1_kernel(int n) {
    __shared__ int warp_sums[32];
    int tid = threadIdx.x, lane = tid & 31, wid = tid >> 5;
    int i = blockIdx.x * SCAN_TILE + tid;
    int v = (i < n) ? g_count[i] : 0;
    int incl = v;
    #pragma unroll
    for (int o = 1; o < 32; o <<= 1) {
        int t = __shfl_up_sync(0xffffffffu, incl, o);
        if (lane >= o) incl += t;
    }
    if (lane == 31) warp_sums[wid] = incl;
    __syncthreads();
    if (wid == 0) {
        int s = warp_sums[lane];
        int sincl = s;
        #pragma unroll
        for (int o = 1; o < 32; o <<= 1) {
            int t = __shfl_up_sync(0xffffffffu, sincl, o);
            if (lane >= o) sincl += t;
        }
        warp_sums[lane] = sincl - s;
        if (lane == 31) g_bsum[blockIdx.x] = sincl;
    }
    __syncthreads();
    int excl = warp_sums[wid] + incl - v;
    if (i < n) {
        g_rowptr[i] = excl;
        g_count[i] = 0;          // self-clean
    }
}

// Phase 3: one 1024-block per tile (t = blockIdx.x). Adds tile offset
// (sum of g_bsum[j<t], warp-computed, no polling), fills cursor, computes dis,
// zeroes g_deg; rowptr[n] = E.
__global__ void scan_phase3_kernel(int n, int nb, int E) {
    __shared__ int s_off;
    int t = blockIdx.x;
    int i = t * SCAN_TILE + threadIdx.x;
    if (threadIdx.x < 32) {
        int lane = threadIdx.x;
        int v0 = (lane < t) ? g_bsum[lane] : 0;
        int v1 = (lane + 32 < t) ? g_bsum[lane + 32] : 0;
        int s = v0 + v1;
        #pragma unroll
        for (int o = 16; o > 0; o >>= 1) s += __shfl_xor_sync(0xffffffffu, s, o);
        if (lane == 0) s_off = s;
    }
    __syncthreads();
    if (i >= n) return;
    int val = g_rowptr[i] + s_off;
    g_rowptr[i] = val;
    g_cursor[i] = val;
    float d = g_deg[i];
    g_dis[i] = (d > 0.0f) ? rsqrtf(d) : 0.0f;
    g_deg[i] = 0.0f;             // self-clean
    if (i == 0) g_rowptr[n] = E;
}

__global__ void scatter_kernel(const int* __restrict__ ei,
                               const float* __restrict__ ew, int E) {
    int e = blockIdx.x * blockDim.x + threadIdx.x;
    if (e >= E) return;
    int r = ei[e], c = ei[E + e];
    float nrm = -g_dis[r] * ew[e] * g_dis[c];
    int p = atomicAdd(&g_cursor[c], 1);
    g_edge[p] = make_int2(r, __float_as_int(nrm));
}

// warp-per-node gather propagation over dense CSR.
// Edge meta one-per-lane + shfl broadcast; feature loads 8 in flight.
// pass 0 also converts the node's own x row into A columns [0,64) (hi/lo).
__global__ void prop_kernel(const float* __restrict__ xin, int pass, int n) {
    int warp = (blockIdx.x * blockDim.x + threadIdx.x) >> 5;
    int lane = threadIdx.x & 31;
    if (warp >= n) return;
    const float2* __restrict__ feat =
        reinterpret_cast<const float2*>(pass ? g_tx1 : xin);
    int s = g_rowptr[warp], e = g_rowptr[warp + 1];
    float a0 = 0.0f, a1 = 0.0f;
    for (int base = s; base < e; base += 32) {
        int idx = base + lane;
        int2 m = (idx < e) ? __ldg(&g_edge[idx]) : make_int2(0, 0);
        int cnt = min(32, e - base);
        for (int q0 = 0; q0 < cnt; q0 += 8) {
            float2 f[8];
            float wq[8];
            #pragma unroll
            for (int q = 0; q < 8; q++) {
                int src = __shfl_sync(0xffffffffu, m.x, q0 + q);
                wq[q] = __int_as_float(__shfl_sync(0xffffffffu, m.y, q0 + q));
                f[q] = __ldg(&feat[src * 32 + lane]);
            }
            #pragma unroll
            for (int q = 0; q < 8; q++) {
                a0 += wq[q] * f[q].x;
                a1 += wq[q] * f[q].y;
            }
        }
    }
    if (pass == 0) {   // tx1 fp32 needed by pass 1 (same float2 layout)
        reinterpret_cast<float2*>(g_tx1)[warp * 32 + lane] = make_float2(a0, a1);
        // fused convert of own x row -> A cols [0,64)
        float2 xv = __ldg(&feat[warp * 32 + lane]);
        __nv_bfloat16 xh0 = __float2bfloat16_rn(xv.x);
        __nv_bfloat16 xh1 = __float2bfloat16_rn(xv.y);
        __nv_bfloat162 xhi; xhi.x = xh0; xhi.y = xh1;
        __nv_bfloat162 xlo;
        xlo.x = __float2bfloat16_rn(xv.x - __bfloat162float(xh0));
        xlo.y = __float2bfloat16_rn(xv.y - __bfloat162float(xh1));
        *reinterpret_cast<__nv_bfloat162*>(g_Ahi + warp * KTOT + 2 * lane) = xhi;
        *reinterpret_cast<__nv_bfloat162*>(g_Alo + warp * KTOT + 2 * lane) = xlo;
    }
    int cbase = pass ? 128 : 64;
    __nv_bfloat16 h0 = __float2bfloat16_rn(a0);
    __nv_bfloat16 h1 = __float2bfloat16_rn(a1);
    __nv_bfloat162 hi; hi.x = h0; hi.y = h1;
    __nv_bfloat162 lo;
    lo.x = __float2bfloat16_rn(a0 - __bfloat162float(h0));
    lo.y = __float2bfloat16_rn(a1 - __bfloat162float(h1));
    *reinterpret_cast<__nv_bfloat162*>(g_Ahi + warp * KTOT + cbase + 2 * lane) = hi;
    *reinterpret_cast<__nv_bfloat162*>(g_Alo + warp * KTOT + cbase + 2 * lane) = lo;
}

__device__ __forceinline__ float sigm(float v) { return 1.0f / (1.0f + expf(-v)); }

// ---------------- HMMA bf16x3 GEMM + fused weights + GRU/head epilogue ----
// SMEM rows padded to 400B (rotates 16B per row across banks -> conflict-free LDSM)
#define SA_B 400
#define SM_AHI 0
#define SM_ALO 51200
#define SM_BHI 102400
#define SM_BLO 153600
#define SM_BIAS 204800
#define GSM_TOTAL (204800 + 512)
#define SC 132            // C f32 row stride

__global__ __launch_bounds__(256, 1)
void gemm_kernel(const float* __restrict__ Wxz,
                 const float* __restrict__ bxz,
                 const float* __restrict__ bhz,
                 const float* __restrict__ Wxh,
                 const float* __restrict__ bxh,
                 const float* __restrict__ bhh,
                 const float* __restrict__ Wlin,
                 const float* __restrict__ blin,
                 float* __restrict__ out, int n) {
    extern __shared__ char smem[];
    uint32_t sbase = smem_u32(smem);
    int tid = threadIdx.x, lane = tid & 31, wid = tid >> 5;
    int row0 = blockIdx.x * 128;

    // stage A (hi/lo) into padded SMEM
    for (int it = tid; it < 3072; it += 256) {
        int r = it / 24, c = it % 24;
        int rg = row0 + r;
        uint4 vh = make_uint4(0, 0, 0, 0), vl = make_uint4(0, 0, 0, 0);
        if (rg < n) {
            vh = *reinterpret_cast<const uint4*>(g_Ahi + rg * KTOT + c * 8);
            vl = *reinterpret_cast<const uint4*>(g_Alo + rg * KTOT + c * 8);
        }
        *reinterpret_cast<uint4*>(smem + SM_AHI + r * SA_B + c * 16) = vh;
        *reinterpret_cast<uint4*>(smem + SM_ALO + r * SA_B + c * 16) = vl;
    }
    // build combined weights in-CTA: raw fp32 W (L2-hot) -> bf16 hi/lo SMEM B [n][k]
    for (int idx = tid; idx < KTOT * NOUT; idx += 256) {
        int k = idx >> 7, nn = idx & 127;
        int seg = k >> 6, i = k & 63;
        const float* W = (nn < 64) ? Wxz : Wxh;
        int j = nn & 63;
        float v;
        if (seg == 0)      v = __ldg(&W[i * 64 + j]) - __ldg(&W[(128 + i) * 64 + j]);
        else if (seg == 1) v = __ldg(&W[(64 + i) * 64 + j]);
        else               v = 2.0f * __ldg(&W[(128 + i) * 64 + j]);
        __nv_bfloat16 hi = __float2bfloat16_rn(v);
        float lo = v - __bfloat162float(hi);
        *reinterpret_cast<__nv_bfloat16*>(smem + SM_BHI + nn * SA_B + k * 2) = hi;
        *reinterpret_cast<__nv_bfloat16*>(smem + SM_BLO + nn * SA_B + k * 2) =
            __float2bfloat16_rn(lo);
    }
    // biases into SMEM
    float* s_bz = reinterpret_cast<float*>(smem + SM_BIAS);
    float* s_bh = s_bz + 64;
    if (tid < 64)       s_bz[tid] = __ldg(&bxz[tid]) + __ldg(&bhz[tid]);
    else if (tid < 128) s_bh[tid - 64] = __ldg(&bxh[tid - 64]) + __ldg(&bhh[tid - 64]);
    __syncthreads();

    // warp tiling: 4x2 warps, each 32(M) x 64(N)
    int m0 = (wid & 3) * 32, n0 = (wid >> 2) * 64;
    int a_r = (lane & 7) + ((lane >> 3) & 1) * 8;
    int a_k = ((lane >> 4) & 1) * 8;
    int b_r = (lane & 7) + ((lane >> 4) & 1) * 8;
    int b_k = ((lane >> 3) & 1) * 8;

    float acc[2][8][4];
    #pragma unroll
    for (int i = 0; i < 2; i++)
        #pragma unroll
        for (int j = 0; j < 8; j++)
            #pragma unroll
            for (int q = 0; q < 4; q++) acc[i][j][q] = 0.0f;

    #pragma unroll
    for (int pass = 0; pass < 3; pass++) {
        uint32_t abase = sbase + ((pass == 2) ? SM_ALO : SM_AHI);
        uint32_t bbase = sbase + ((pass == 1) ? SM_BLO : SM_BHI);
        uint32_t aaddr0 = abase + (uint32_t)((m0 + a_r) * SA_B + a_k * 2);
        uint32_t aaddr1 = aaddr0 + 16 * SA_B;
        uint32_t baddr0 = bbase + (uint32_t)((n0 + b_r) * SA_B + b_k * 2);
        #pragma unroll
        for (int k = 0; k < KTOT; k += 16) {
            uint32_t a0[4], a1[4], bb[4][4];
            ldsm4(a0, aaddr0 + k * 2);
            ldsm4(a1, aaddr1 + k * 2);
            #pragma unroll
            for (int g = 0; g < 4; g++)
                ldsm4(bb[g], baddr0 + (uint32_t)(g * 16 * SA_B) + k * 2);
            #pragma unroll
            for (int g = 0; g < 4; g++) {
                mma_bf16(acc[0][2 * g],     a0, bb[g][0], bb[g][1]);
                mma_bf16(acc[0][2 * g + 1], a0, bb[g][2], bb[g][3]);
                mma_bf16(acc[1][2 * g],     a1, bb[g][0], bb[g][1]);
                mma_bf16(acc[1][2 * g + 1], a1, bb[g][2], bb[g][3]);
            }
        }
    }
    __syncthreads();

    // write C fragments to SMEM (reuses A region; 128 x 132 f32 = 67.6 KB)
    float* C = reinterpret_cast<float*>(smem);
    #pragma unroll
    for (int ms = 0; ms < 2; ms++) {
        #pragma unroll
        for (int ns = 0; ns < 8; ns++) {
            int r = m0 + ms * 16 + (lane >> 2);
            int c = n0 + ns * 8 + (lane & 3) * 2;
            float2 v0 = make_float2(acc[ms][ns][0], acc[ms][ns][1]);
            float2 v1 = make_float2(acc[ms][ns][2], acc[ms][ns][3]);
            *reinterpret_cast<float2*>(C + r * SC + c) = v0;
            *reinterpret_cast<float2*>(C + (r + 8) * SC + c) = v1;
        }
    }
    __syncthreads();

    // fused epilogue: one thread per row
    if (tid < 128) {
        int r = row0 + tid;
        const float* Cr = C + tid * SC;
        float s0 = 0.0f, s1 = 0.0f;
        #pragma unroll 4
        for (int j = 0; j < 64; j++) {
            float z = sigm(Cr[j] + s_bz[j]);
            float t = tanhf(Cr[j + 64] + s_bh[j]);
            float u = tanhf((1.0f - z) * t);
            s0 += u * __ldg(&Wlin[j * 2 + 0]);
            s1 += u * __ldg(&Wlin[j * 2 + 1]);
        }
        if (r < n) {
            out[r * 2 + 0] = sigm(s0 + __ldg(&blin[0]));
            out[r * 2 + 1] = sigm(s1 + __ldg(&blin[1]));
        }
    }
}

// ---------------- launch ----------------
extern "C" void kernel_launch(void* const* d_in, const int* in_sizes, int n_in,
                              void* d_out, int out_size) {
    const float* x    = (const float*)d_in[0];
    const int*   ei   = (const int*)d_in[1];
    const float* ew   = (const float*)d_in[2];
    const float* Wxz  = (const float*)d_in[3];
    const float* bxz  = (const float*)d_in[4];
    const float* bhz  = (const float*)d_in[6];
    const float* Wxh  = (const float*)d_in[11];
    const float* bxh  = (const float*)d_in[12];
    const float* bhh  = (const float*)d_in[14];
    const float* Wlin = (const float*)d_in[15];
    const float* blin = (const float*)d_in[16];
    float* out = (float*)d_out;

    int n = in_sizes[0] / F;       // 50000
    int E = in_sizes[2];           // 800000
    int nb = (n + SCAN_TILE - 1) / SCAN_TILE;

    cudaFuncSetAttribute(gemm_kernel, cudaFuncAttributeMaxDynamicSharedMemorySize, GSM_TOTAL);

    edge_pass1_kernel<<<(E + 255) / 256, 256>>>(ei, ew, E);
    scan_phase1_kernel<<<nb, SCAN_TILE>>>(n);
    scan_phase3_kernel<<<nb, SCAN_TILE>>>(n, nb, E);
    scatter_kernel<<<(E + 255) / 256, 256>>>(ei, ew, E);

    int prop_blocks = (n * 32 + 255) / 256;
    prop_kernel<<<prop_blocks, 256>>>(x, 0, n);
    prop_kernel<<<prop_blocks, 256>>>(x, 1, n);

    gemm_kernel<<<(n + 127) / 128, 256, GSM_TOTAL>>>(
        Wxz, bxz, bhz, Wxh, bxh, bhh, Wlin, blin, out, n);
    (void)n_in; (void)out_size;
}

// round 14
// speedup vs baseline: 1.3964x; 1.3964x over previous
#include <cuda_runtime.h>
#include <cuda_bf16.h>
#include <cstdint>
#include <math.h>

#define N_NODES 50000
#define N_EDGES 800000
#define F 64          // F_IN == F_HID
#define KTOT 192      // x | tx1 | y
#define NOUT 128      // z (64) | h (64)
#define SCAN_TILE 1024
#define MAX_BLOCKS ((N_NODES + SCAN_TILE - 1) / SCAN_TILE + 1)

// ---------------- device scratch (allocation-free) ----------------
// Self-clean invariant: scan_phase1 zeroes g_count, scan_phase3 zeroes g_deg,
// so every kernel_launch call leaves them zeroed for the next call.
__device__ float g_deg[N_NODES];
__device__ float g_dis[N_NODES];
__device__ int   g_count[N_NODES];
__device__ int   g_rowptr[N_NODES + 1];
__device__ int   g_cursor[N_NODES];
__device__ int   g_bsum[MAX_BLOCKS];
__device__ __align__(16) int2 g_edge[N_EDGES];      // (src, norm-bits), dense CSR
__device__ __align__(16) float g_tx1[N_NODES * F];
__device__ __align__(16) __nv_bfloat16 g_Ahi[N_NODES * KTOT];
__device__ __align__(16) __nv_bfloat16 g_Alo[N_NODES * KTOT];
__device__ __align__(16) __nv_bfloat16 g_Bhi[NOUT * KTOT];   // [n][k], k-contiguous
__device__ __align__(16) __nv_bfloat16 g_Blo[NOUT * KTOT];
__device__ float g_bz[F];
__device__ float g_bh[F];

// ---------------- PTX helpers ----------------
__device__ __forceinline__ uint32_t smem_u32(const void* p) {
    uint32_t a;
    asm("{ .reg .u64 t; cvta.to.shared.u64 t, %1; cvt.u32.u64 %0, t; }" : "=r"(a) : "l"(p));
    return a;
}
__device__ __forceinline__ void ldsm4(uint32_t (&d)[4], uint32_t addr) {
    asm volatile("ldmatrix.sync.aligned.m8n8.x4.shared.b16 {%0,%1,%2,%3}, [%4];\n"
                 : "=r"(d[0]), "=r"(d[1]), "=r"(d[2]), "=r"(d[3]) : "r"(addr));
}
__device__ __forceinline__ void mma_bf16(float (&c)[4], const uint32_t (&a)[4],
                                         uint32_t b0, uint32_t b1) {
    asm volatile(
        "mma.sync.aligned.m16n8k16.row.col.f32.bf16.bf16.f32 "
        "{%0,%1,%2,%3}, {%4,%5,%6,%7}, {%8,%9}, {%0,%1,%2,%3};\n"
        : "+f"(c[0]), "+f"(c[1]), "+f"(c[2]), "+f"(c[3])
        : "r"(a[0]), "r"(a[1]), "r"(a[2]), "r"(a[3]), "r"(b0), "r"(b1));
}

// ---------------- kernels ----------------

// 2 edges per thread: fewer blocks, more MLP; atomics unchanged.
__global__ void edge_pass1_kernel(const int* __restrict__ ei,
                                  const float* __restrict__ ew, int E) {
    int e = (blockIdx.x * blockDim.x + threadIdx.x) * 2;
    if (e >= E) return;
    int r0 = ei[e];
    int c0 = ei[E + e];
    float w0 = ew[e];
    if (e + 1 < E) {
        int r1 = ei[e + 1];
        int c1 = ei[E + e + 1];
        float w1 = ew[e + 1];
        atomicAdd(&g_deg[r0], w0);
        atomicAdd(&g_deg[r1], w1);
        atomicAdd(&g_count[c0], 1);
        atomicAdd(&g_count[c1], 1);
    } else {
        atomicAdd(&g_deg[r0], w0);
        atomicAdd(&g_count[c0], 1);
    }
}

// Phase 1: per-1024-tile local exclusive scan; tile total -> g_bsum.
// Also zeroes g_count (self-clean for next replay).
__global__ void scan_phase1_kernel(int n) {
    __shared__ int warp_sums[32];
    int tid = threadIdx.x, lane = tid & 31, wid = tid >> 5;
    int i = blockIdx.x * SCAN_TILE + tid;
    int v = (i < n) ? g_count[i] : 0;
    int incl = v;
    #pragma unroll
    for (int o = 1; o < 32; o <<= 1) {
        int t = __shfl_up_sync(0xffffffffu, incl, o);
        if (lane >= o) incl += t;
    }
    if (lane == 31) warp_sums[wid] = incl;
    __syncthreads();
    if (wid == 0) {
        int s = warp_sums[lane];
        int sincl = s;
        #pragma unroll
        for (int o = 1; o < 32; o <<= 1) {
            int t = __shfl_up_sync(0xffffffffu, sincl, o);
            if (lane >= o) sincl += t;
        }
        warp_sums[lane] = sincl - s;
        if (lane == 31) g_bsum[blockIdx.x] = sincl;
    }
    __syncthreads();
    int excl = warp_sums[wid] + incl - v;
    if (i < n) {
        g_rowptr[i] = excl;
        g_count[i] = 0;          // self-clean
    }
}

// Phase 3: one 1024-block per tile (t = blockIdx.x). Adds tile offset
// (sum of g_bsum[j<t], warp-computed, no polling), fills cursor, computes dis,
// zeroes g_deg; rowptr[n] = E.
__global__ void scan_phase3_kernel(int n, int nb, int E) {
    __shared__ int s_off;
    int t = blockIdx.x;
    int i = t * SCAN_TILE + threadIdx.x;
    if (threadIdx.x < 32) {
        int lane = threadIdx.x;
        int v0 = (lane < t) ? g_bsum[lane] : 0;
        int v1 = (lane + 32 < t) ? g_bsum[lane + 32] : 0;
        int s = v0 + v1;
        #pragma unroll
        for (int o = 16; o > 0; o >>= 1) s += __shfl_xor_sync(0xffffffffu, s, o);
        if (lane == 0) s_off = s;
    }
    __syncthreads();
    if (i >= n) return;
    int val = g_rowptr[i] + s_off;
    g_rowptr[i] = val;
    g_cursor[i] = val;
    float d = g_deg[i];
    g_dis[i] = (d > 0.0f) ? rsqrtf(d) : 0.0f;
    g_deg[i] = 0.0f;             // self-clean
    if (i == 0) g_rowptr[n] = E;
}

__global__ void scatter_kernel(const int* __restrict__ ei,
                               const float* __restrict__ ew, int E) {
    int e = blockIdx.x * blockDim.x + threadIdx.x;
    if (e >= E) return;
    int r = ei[e], c = ei[E + e];
    float nrm = -g_dis[r] * ew[e] * g_dis[c];
    int p = atomicAdd(&g_cursor[c], 1);
    g_edge[p] = make_int2(r, __float_as_int(nrm));
}

// warp-per-node gather propagation over dense CSR.
// Edge meta one-per-lane + shfl broadcast; feature loads 8 in flight.
// pass 0 also converts the node's own x row into A columns [0,64) (hi/lo).
__global__ void prop_kernel(const float* __restrict__ xin, int pass, int n) {
    int warp = (blockIdx.x * blockDim.x + threadIdx.x) >> 5;
    int lane = threadIdx.x & 31;
    if (warp >= n) return;
    const float2* __restrict__ feat =
        reinterpret_cast<const float2*>(pass ? g_tx1 : xin);
    int s = g_rowptr[warp], e = g_rowptr[warp + 1];
    float a0 = 0.0f, a1 = 0.0f;
    for (int base = s; base < e; base += 32) {
        int idx = base + lane;
        int2 m = (idx < e) ? __ldg(&g_edge[idx]) : make_int2(0, 0);
        int cnt = min(32, e - base);
        for (int q0 = 0; q0 < cnt; q0 += 8) {
            float2 f[8];
            float wq[8];
            #pragma unroll
            for (int q = 0; q < 8; q++) {
                int src = __shfl_sync(0xffffffffu, m.x, q0 + q);
                wq[q] = __int_as_float(__shfl_sync(0xffffffffu, m.y, q0 + q));
                f[q] = __ldg(&feat[src * 32 + lane]);
            }
            #pragma unroll
            for (int q = 0; q < 8; q++) {
                a0 += wq[q] * f[q].x;
                a1 += wq[q] * f[q].y;
            }
        }
    }
    if (pass == 0) {   // tx1 fp32 needed by pass 1 (same float2 layout)
        reinterpret_cast<float2*>(g_tx1)[warp * 32 + lane] = make_float2(a0, a1);
        // fused convert of own x row -> A cols [0,64)
        float2 xv = __ldg(&feat[warp * 32 + lane]);
        __nv_bfloat16 xh0 = __float2bfloat16_rn(xv.x);
        __nv_bfloat16 xh1 = __float2bfloat16_rn(xv.y);
        __nv_bfloat162 xhi; xhi.x = xh0; xhi.y = xh1;
        __nv_bfloat162 xlo;
        xlo.x = __float2bfloat16_rn(xv.x - __bfloat162float(xh0));
        xlo.y = __float2bfloat16_rn(xv.y - __bfloat162float(xh1));
        *reinterpret_cast<__nv_bfloat162*>(g_Ahi + warp * KTOT + 2 * lane) = xhi;
        *reinterpret_cast<__nv_bfloat162*>(g_Alo + warp * KTOT + 2 * lane) = xlo;
    }
    int cbase = pass ? 128 : 64;
    __nv_bfloat16 h0 = __float2bfloat16_rn(a0);
    __nv_bfloat16 h1 = __float2bfloat16_rn(a1);
    __nv_bfloat162 hi; hi.x = h0; hi.y = h1;
    __nv_bfloat162 lo;
    lo.x = __float2bfloat16_rn(a0 - __bfloat162float(h0));
    lo.y = __float2bfloat16_rn(a1 - __bfloat162float(h1));
    *reinterpret_cast<__nv_bfloat162*>(g_Ahi + warp * KTOT + cbase + 2 * lane) = hi;
    *reinterpret_cast<__nv_bfloat162*>(g_Alo + warp * KTOT + cbase + 2 * lane) = lo;
}

// build combined weights -> bf16 hi/lo B stored [n][k] ; biases
__global__ void weights_kernel(const float* __restrict__ Wxz,
                               const float* __restrict__ bxz,
                               const float* __restrict__ bhz,
                               const float* __restrict__ Wxh,
                               const float* __restrict__ bxh,
                               const float* __restrict__ bhh) {
    int idx = blockIdx.x * blockDim.x + threadIdx.x;
    if (idx < KTOT * NOUT) {
        int k = idx / NOUT, nn = idx % NOUT;
        int seg = k / 64, i = k % 64;
        const float* W = (nn < 64) ? Wxz : Wxh;
        int j = (nn < 64) ? nn : (nn - 64);
        float v;
        if (seg == 0)      v = W[(0 * 64 + i) * 64 + j] - W[(2 * 64 + i) * 64 + j];
        else if (seg == 1) v = W[(1 * 64 + i) * 64 + j];
        else               v = 2.0f * W[(2 * 64 + i) * 64 + j];
        __nv_bfloat16 hi = __float2bfloat16_rn(v);
        float lo = v - __bfloat162float(hi);
        g_Bhi[nn * KTOT + k] = hi;
        g_Blo[nn * KTOT + k] = __float2bfloat16_rn(lo);
    }
    if (blockIdx.x == 0 && threadIdx.x < F) {
        g_bz[threadIdx.x] = bxz[threadIdx.x] + bhz[threadIdx.x];
        g_bh[threadIdx.x] = bxh[threadIdx.x] + bhh[threadIdx.x];
    }
}

__device__ __forceinline__ float sigm(float v) { return 1.0f / (1.0f + expf(-v)); }

// ---------------- HMMA bf16x3 GEMM + fused GRU/head epilogue ----------------
// SMEM rows padded to 400B (rotates 16B per row across banks -> conflict-free LDSM)
#define SA_B 400
#define SM_AHI 0
#define SM_ALO 51200
#define SM_BHI 102400
#define SM_BLO 153600
#define GSM_TOTAL 204800
#define SC 132            // C f32 row stride

__global__ __launch_bounds__(256, 1)
void gemm_kernel(const float* __restrict__ Wlin,
                 const float* __restrict__ blin,
                 float* __restrict__ out, int n) {
    extern __shared__ char smem[];
    uint32_t sbase = smem_u32(smem);
    int tid = threadIdx.x, lane = tid & 31, wid = tid >> 5;
    int row0 = blockIdx.x * 128;

    // stage A (hi/lo) and B (hi/lo) into padded SMEM
    for (int it = tid; it < 3072; it += 256) {
        int r = it / 24, c = it % 24;
        int rg = row0 + r;
        uint4 vh = make_uint4(0, 0, 0, 0), vl = make_uint4(0, 0, 0, 0);
        if (rg < n) {
            vh = *reinterpret_cast<const uint4*>(g_Ahi + rg * KTOT + c * 8);
            vl = *reinterpret_cast<const uint4*>(g_Alo + rg * KTOT + c * 8);
        }
        *reinterpret_cast<uint4*>(smem + SM_AHI + r * SA_B + c * 16) = vh;
        *reinterpret_cast<uint4*>(smem + SM_ALO + r * SA_B + c * 16) = vl;
        uint4 bh = *reinterpret_cast<const uint4*>(g_Bhi + r * KTOT + c * 8);
        uint4 bl = *reinterpret_cast<const uint4*>(g_Blo + r * KTOT + c * 8);
        *reinterpret_cast<uint4*>(smem + SM_BHI + r * SA_B + c * 16) = bh;
        *reinterpret_cast<uint4*>(smem + SM_BLO + r * SA_B + c * 16) = bl;
    }
    __syncthreads();

    // warp tiling: 4x2 warps, each 32(M) x 64(N)
    int m0 = (wid & 3) * 32, n0 = (wid >> 2) * 64;
    int a_r = (lane & 7) + ((lane >> 3) & 1) * 8;
    int a_k = ((lane >> 4) & 1) * 8;
    int b_r = (lane & 7) + ((lane >> 4) & 1) * 8;
    int b_k = ((lane >> 3) & 1) * 8;

    float acc[2][8][4];
    #pragma unroll
    for (int i = 0; i < 2; i++)
        #pragma unroll
        for (int j = 0; j < 8; j++)
            #pragma unroll
            for (int q = 0; q < 4; q++) acc[i][j][q] = 0.0f;

    #pragma unroll
    for (int pass = 0; pass < 3; pass++) {
        uint32_t abase = sbase + ((pass == 2) ? SM_ALO : SM_AHI);
        uint32_t bbase = sbase + ((pass == 1) ? SM_BLO : SM_BHI);
        uint32_t aaddr0 = abase + (uint32_t)((m0 + a_r) * SA_B + a_k * 2);
        uint32_t aaddr1 = aaddr0 + 16 * SA_B;
        uint32_t baddr0 = bbase + (uint32_t)((n0 + b_r) * SA_B + b_k * 2);
        #pragma unroll
        for (int k = 0; k < KTOT; k += 16) {
            uint32_t a0[4], a1[4], bb[4][4];
            ldsm4(a0, aaddr0 + k * 2);
            ldsm4(a1, aaddr1 + k * 2);
            #pragma unroll
            for (int g = 0; g < 4; g++)
                ldsm4(bb[g], baddr0 + (uint32_t)(g * 16 * SA_B) + k * 2);
            #pragma unroll
            for (int g = 0; g < 4; g++) {
                mma_bf16(acc[0][2 * g],     a0, bb[g][0], bb[g][1]);
                mma_bf16(acc[0][2 * g + 1], a0, bb[g][2], bb[g][3]);
                mma_bf16(acc[1][2 * g],     a1, bb[g][0], bb[g][1]);
                mma_bf16(acc[1][2 * g + 1], a1, bb[g][2], bb[g][3]);
            }
        }
    }
    __syncthreads();

    // write C fragments to SMEM (reuses A region; 128 x 132 f32 = 67.6 KB)
    float* C = reinterpret_cast<float*>(smem);
    #pragma unroll
    for (int ms = 0; ms < 2; ms++) {
        #pragma unroll
        for (int ns = 0; ns < 8; ns++) {
            int r = m0 + ms * 16 + (lane >> 2);
            int c = n0 + ns * 8 + (lane & 3) * 2;
            float2 v0 = make_float2(acc[ms][ns][0], acc[ms][ns][1]);
            float2 v1 = make_float2(acc[ms][ns][2], acc[ms][ns][3]);
            *reinterpret_cast<float2*>(C + r * SC + c) = v0;
            *reinterpret_cast<float2*>(C + (r + 8) * SC + c) = v1;
        }
    }
    __syncthreads();

    // fused epilogue: one thread per row
    if (tid < 128) {
        int r = row0 + tid;
        const float* Cr = C + tid * SC;
        float s0 = 0.0f, s1 = 0.0f;
        #pragma unroll 4
        for (int j = 0; j < 64; j++) {
            float z = sigm(Cr[j] + __ldg(&g_bz[j]));
            float t = tanhf(Cr[j + 64] + __ldg(&g_bh[j]));
            float u = tanhf((1.0f - z) * t);
            s0 += u * __ldg(&Wlin[j * 2 + 0]);
            s1 += u * __ldg(&Wlin[j * 2 + 1]);
        }
        if (r < n) {
            out[r * 2 + 0] = sigm(s0 + __ldg(&blin[0]));
            out[r * 2 + 1] = sigm(s1 + __ldg(&blin[1]));
        }
    }
}

// ---------------- launch ----------------
extern "C" void kernel_launch(void* const* d_in, const int* in_sizes, int n_in,
                              void* d_out, int out_size) {
    const float* x    = (const float*)d_in[0];
    const int*   ei   = (const int*)d_in[1];
    const float* ew   = (const float*)d_in[2];
    const float* Wxz  = (const float*)d_in[3];
    const float* bxz  = (const float*)d_in[4];
    const float* bhz  = (const float*)d_in[6];
    const float* Wxh  = (const float*)d_in[11];
    const float* bxh  = (const float*)d_in[12];
    const float* bhh  = (const float*)d_in[14];
    const float* Wlin = (const float*)d_in[15];
    const float* blin = (const float*)d_in[16];
    float* out = (float*)d_out;

    int n = in_sizes[0] / F;       // 50000
    int E = in_sizes[2];           // 800000
    int nb = (n + SCAN_TILE - 1) / SCAN_TILE;

    cudaFuncSetAttribute(gemm_kernel, cudaFuncAttributeMaxDynamicSharedMemorySize, GSM_TOTAL);

    edge_pass1_kernel<<<(E / 2 + 255) / 256, 256>>>(ei, ew, E);
    scan_phase1_kernel<<<nb, SCAN_TILE>>>(n);
    scan_phase3_kernel<<<nb, SCAN_TILE>>>(n, nb, E);
    scatter_kernel<<<(E + 255) / 256, 256>>>(ei, ew, E);

    int prop_blocks = (n * 32 + 255) / 256;
    prop_kernel<<<prop_blocks, 256>>>(x, 0, n);
    prop_kernel<<<prop_blocks, 256>>>(x, 1, n);

    weights_kernel<<<(KTOT * NOUT + 255) / 256, 256>>>(Wxz, bxz, bhz, Wxh, bxh, bhh);
    gemm_kernel<<<(n + 127) / 128, 256, GSM_TOTAL>>>(Wlin, blin, out, n);
    (void)n_in; (void)out_size;
}